// round 16
// baseline (speedup 1.0000x reference)
#include <cuda_runtime.h>

// ---------------------------------------------------------------------------
// AutoregressiveGRUWithAttention  (B=1024, L=64, T=128, IN=13, H=64, OUT=13)
//
// R15 = R13 phase structure, Wfusion deleted and A rebalanced:
//   Phase A (decoder): EVERY thread owns ONE register row:
//       tid 0-191: Whh row tid  (on h)  -> gh plane
//       tid 192-255: Wa row tid-192 (on o) -> slg
//     plus threads 0-103: one Wf dot (oc=tid>>3, b=tid&7) on o from smem
//       -> y(t-1) -> snin + gmem out.
//   Phase B: thread owns (bb, j) and (bb+4, j); computes gi = Wih·y(t-1)
//     from REGISTER-resident Wih rows (39 regs), folds online softmax,
//     GRU gates, publishes h/o. 2 syncs/step.
// Decoder A(0) computes y from o_init == nin, so no special prologue.
// Online-softmax attention == reference masked softmax (validated R7-R14).
// ---------------------------------------------------------------------------

typedef unsigned long long ull;

namespace {
constexpr int L_ = 64, T_ = 128, IN_ = 13, H_ = 64, OUT_ = 13, NB_ = 8;
constexpr int THREADS_ = 256, BLOCKS_ = 128;
constexpr int HS_ = 68;              // state row stride
constexpr int GP_ = NB_ * HS_;       // 544 floats per gate plane
constexpr int XT_ = 16, XPB_ = L_ * XT_;

constexpr int SM_SH  = 0;                 // h   [8][68]
constexpr int SM_SO  = SM_SH + GP_;       // o   [8][68]
constexpr int SM_GH  = SM_SO + GP_;       // Whh.h [3][8][68]
constexpr int SM_LG  = SM_GH + 3 * GP_;   // logits [8][68]
constexpr int SM_NIN = SM_LG + GP_;       // y_prev [8][16]
constexpr int SM_WF  = SM_NIN + NB_ * 16; // Wf [13][68]
constexpr int SM_SX  = SM_WF + 13 * HS_;  // x [8][1024]
constexpr int SM_FLOATS = SM_SX + NB_ * XPB_;   // 11924 floats = 47.7 KB
}

__device__ __forceinline__ ull fma2_(ull a, ull b, ull c) {
    ull d;
    asm("fma.rn.f32x2 %0, %1, %2, %3;" : "=l"(d) : "l"(a), "l"(b), "l"(c));
    return d;
}
__device__ __forceinline__ float hsum2_(ull a) {
    unsigned lo, hi;
    asm("mov.b64 {%0, %1}, %2;" : "=r"(lo), "=r"(hi) : "l"(a));
    return __uint_as_float(lo) + __uint_as_float(hi);
}
__device__ __forceinline__ float sigmoid_(float a) {
    return __fdividef(1.f, 1.f + __expf(-a));
}
__device__ __forceinline__ float tanh_(float a) {
    float c  = fminf(fmaxf(a, -15.f), 15.f);
    float e2 = __expf(2.f * c);
    return __fdividef(e2 - 1.f, e2 + 1.f);
}

// One register row dotted with 8 state vectors (warp-broadcast smem reads),
// results to dst[b*HS_]. 4 accumulator chains per half for ILP.
__device__ __forceinline__ void dots8_row(const ull (&w)[32], const float* src,
                                          float* dst) {
    #pragma unroll
    for (int bq = 0; bq < 2; ++bq) {
        const float* p0 = src + (4 * bq + 0) * HS_;
        const float* p1 = src + (4 * bq + 1) * HS_;
        const float* p2 = src + (4 * bq + 2) * HS_;
        const float* p3 = src + (4 * bq + 3) * HS_;
        ull a0 = 0, a1 = 0, a2 = 0, a3 = 0;
        #pragma unroll
        for (int c = 0; c < 16; ++c) {
            ulonglong2 v0 = *(const ulonglong2*)(p0 + 4 * c);
            ulonglong2 v1 = *(const ulonglong2*)(p1 + 4 * c);
            ulonglong2 v2 = *(const ulonglong2*)(p2 + 4 * c);
            ulonglong2 v3 = *(const ulonglong2*)(p3 + 4 * c);
            a0 = fma2_(w[2*c], v0.x, a0); a0 = fma2_(w[2*c+1], v0.y, a0);
            a1 = fma2_(w[2*c], v1.x, a1); a1 = fma2_(w[2*c+1], v1.y, a1);
            a2 = fma2_(w[2*c], v2.x, a2); a2 = fma2_(w[2*c+1], v2.y, a2);
            a3 = fma2_(w[2*c], v3.x, a3); a3 = fma2_(w[2*c+1], v3.y, a3);
        }
        dst[(4 * bq + 0) * HS_] = hsum2_(a0);
        dst[(4 * bq + 1) * HS_] = hsum2_(a1);
        dst[(4 * bq + 2) * HS_] = hsum2_(a2);
        dst[(4 * bq + 3) * HS_] = hsum2_(a3);
    }
}

__global__ void __launch_bounds__(THREADS_, 1)
gru_attn_kernel(const float* __restrict__ x, const int* __restrict__ lengths,
                const float* __restrict__ Wih, const float* __restrict__ Whh,
                const float* __restrict__ bih, const float* __restrict__ bhh,
                const float* __restrict__ Wf,  const float* __restrict__ bf,
                const float* __restrict__ Wa,  const float* __restrict__ ba,
                float* __restrict__ out)
{
    __shared__ __align__(16) float sm[SM_FLOATS];
    __shared__ int smax;
    float* sh   = sm + SM_SH;
    float* so   = sm + SM_SO;
    float* gh   = sm + SM_GH;
    float* slg  = sm + SM_LG;
    float* snin = sm + SM_NIN;
    float* sWf  = sm + SM_WF;
    float* sx   = sm + SM_SX;

    const int tid = threadIdx.x;
    const int b0  = blockIdx.x * NB_;
    const int j2  = tid & 63;
    const int bb  = tid >> 6;                  // 0..3
    const int offg[2] = { bb * HS_ + j2, (4 + bb) * HS_ + j2 };

    // ---- staging
    for (int idx = tid; idx < NB_ * XPB_; idx += THREADS_) {
        int b = idx >> 10, r = idx & 1023, tt = r >> 4, i = r & 15;
        sx[idx] = (i < IN_) ? x[(size_t)(b0 + b) * (L_ * IN_) + tt * IN_ + i] : 0.f;
    }
    for (int idx = tid; idx < OUT_ * H_; idx += THREADS_) {
        int r = idx >> 6, c = idx & 63;
        sWf[r * HS_ + c] = Wf[idx];
    }
    for (int idx = tid; idx < GP_; idx += THREADS_) sh[idx] = 0.f;
    if (tid == 0) {
        int m = 0;
        #pragma unroll
        for (int b = 0; b < NB_; ++b) m = max(m, lengths[b0 + b]);
        smax = m;
    }

    // ---- register weights
    ull w2[32];                    // one 64-wide row: Whh (tid<192) or Wa
    {
        const ull* p = (tid < 192) ? (const ull*)(Whh + tid * H_)
                                   : (const ull*)(Wa + (tid - 192) * H_);
        #pragma unroll
        for (int k = 0; k < 32; ++k) w2[k] = p[k];
    }
    float wr_[IN_], wz_[IN_], wn_[IN_];        // Wih rows for channel j2
    #pragma unroll
    for (int i = 0; i < IN_; ++i) {
        wr_[i] = Wih[j2 * IN_ + i];
        wz_[i] = Wih[(64 + j2) * IN_ + i];
        wn_[i] = Wih[(128 + j2) * IN_ + i];
    }
    float* dstA = (tid < 192) ? (gh + (tid >> 6) * GP_ + (tid & 63))
                              : (slg + (tid - 192));

    // Wf-dot role (threads 0-103): oc = tid>>3, batch = tid&7
    const bool wf_act = (tid < 104);
    const int  oc_wf = tid >> 3, b_wf = tid & 7;
    const float bf_reg = wf_act ? bf[oc_wf] : 0.f;

    // ---- Phase-B constants
    const float brr = bih[j2]          + bhh[j2];
    const float bzz = bih[H_ + j2]     + bhh[H_ + j2];
    const float bni = bih[2 * H_ + j2];
    const float bnh = bhh[2 * H_ + j2];
    const float bav = ba[j2];
    const int len_[2] = { lengths[b0 + bb], lengths[b0 + bb + 4] };

    __syncthreads();
    const int Lmax = smax;

    float h_own[2] = {0.f, 0.f};

    // =======================  ENCODER  =======================
    for (int t = 0; t < Lmax; ++t) {
        if (tid < 192) dots8_row(w2, sh, dstA);      // gh = Whh.h
        __syncthreads();
        #pragma unroll
        for (int g = 0; g < 2; ++g) {
            const int b = 4 * g + bb, off = offg[g];
            const float* xv = sx + b * XPB_ + t * XT_;
            float gr = 0.f, gz = 0.f, gn = 0.f;
            #pragma unroll
            for (int i = 0; i < IN_; ++i) {
                float v = xv[i];
                gr += wr_[i] * v; gz += wz_[i] * v; gn += wn_[i] * v;
            }
            float r = sigmoid_(gh[off] + gr + brr);
            float z = sigmoid_(gh[GP_ + off] + gz + bzz);
            float n = tanh_((gn + bni) + r * (gh[2 * GP_ + off] + bnh));
            float hne = (1.f - z) * n + z * h_own[g];
            h_own[g] = (t < len_[g]) ? hne : h_own[g];
            sh[off] = h_own[g];
        }
        __syncthreads();
    }

    // o_init = outs[-1]: nonzero only when length == L (then equals final h)
    so[offg[0]] = (len_[0] == L_) ? h_own[0] : 0.f;
    so[offg[1]] = (len_[1] == L_) ? h_own[1] : 0.f;
    __syncthreads();

    // =======================  DECODER  =======================
    float m_[2] = {-1e30f, -1e30f}, s_[2] = {0.f, 0.f};
    float a_[2] = {0.f, 0.f}, op_[2] = {0.f, 0.f};

    for (int t = 0; t <= T_; ++t) {
        // ---- Phase A on (h(t-1), o(t-1)): gh, slg, y(t-1)
        dots8_row(w2, (tid < 192) ? sh : so, dstA);
        if (wf_act) {
            const ulonglong2* wp = (const ulonglong2*)(sWf + oc_wf * HS_);
            const ulonglong2* op = (const ulonglong2*)(so + b_wf * HS_);
            ull acc = 0;
            #pragma unroll
            for (int c = 0; c < 16; ++c) {
                ulonglong2 wv = wp[c], ov = op[c];
                acc = fma2_(wv.x, ov.x, acc);
                acc = fma2_(wv.y, ov.y, acc);
            }
            float y = hsum2_(acc) + bf_reg;       // y(t-1); at t=0 this is nin
            snin[b_wf * 16 + oc_wf] = y;
            if (t > 0)
                out[((size_t)(b0 + b_wf) * T_ + (t - 1)) * OUT_ + oc_wf] = y;
        }
        __syncthreads();

        // ---- Phase B
        if (t < T_) {
            #pragma unroll
            for (int g = 0; g < 2; ++g) {
                const int b = 4 * g + bb, off = offg[g];
                // gi = Wih . y(t-1)  (register weights, broadcast snin reads)
                const float* yv = snin + b * 16;
                float gr = 0.f, gz = 0.f, gn = 0.f;
                #pragma unroll
                for (int i = 0; i < IN_; ++i) {
                    float v = yv[i];
                    gr += wr_[i] * v; gz += wz_[i] * v; gn += wn_[i] * v;
                }
                // fold buf[t-1] = o(t-1) into online softmax
                float l = slg[off] + bav;
                if (t > 0) {
                    float mn = fmaxf(m_[g], l);
                    float c = __expf(m_[g] - mn), e = __expf(l - mn);
                    s_[g] = s_[g] * c + e;
                    a_[g] = a_[g] * c + e * op_[g];
                    m_[g] = mn;
                }
                float r = sigmoid_(gh[off] + gr + brr);
                float z = sigmoid_(gh[GP_ + off] + gz + bzz);
                float n = tanh_((gn + bni) + r * (gh[2 * GP_ + off] + bnh));
                float hne = (1.f - z) * n + z * h_own[g];
                float att = (t == 0) ? 0.f : __fdividef(a_[g], s_[g]);
                float ov = hne + att;
                h_own[g] = hne;  op_[g] = ov;
                sh[off] = hne;   so[off] = ov;
            }
        }
        __syncthreads();
    }
}

extern "C" void kernel_launch(void* const* d_in, const int* in_sizes, int n_in,
                              void* d_out, int out_size) {
    const float* xp   = nullptr;
    const int*   lenp = nullptr;
    const float *Wihp = nullptr, *Whhp = nullptr, *bihp = nullptr, *bhhp = nullptr;
    const float *Wfp = nullptr, *bfp = nullptr, *Wap = nullptr, *bap = nullptr;

    for (int i = 0; i < n_in; ++i) {
        switch (in_sizes[i]) {
            case 1024 * 64 * 13: xp   = (const float*)d_in[i]; break;
            case 1024:           lenp = (const int*)d_in[i];   break;
            case 192 * 13:       Wihp = (const float*)d_in[i]; break;
            case 192 * 64:       Whhp = (const float*)d_in[i]; break;
            case 192:
                if (!bihp) bihp = (const float*)d_in[i];
                else       bhhp = (const float*)d_in[i];
                break;
            case 13 * 64:        Wfp  = (const float*)d_in[i]; break;
            case 13:             bfp  = (const float*)d_in[i]; break;
            case 64 * 64:        Wap  = (const float*)d_in[i]; break;
            case 64:             bap  = (const float*)d_in[i]; break;
            default: break;   // output_length scalar -> T=128 hardcoded
        }
    }

    gru_attn_kernel<<<BLOCKS_, THREADS_>>>(
        xp, lenp, Wihp, Whhp, bihp, bhhp, Wfp, bfp, Wap, bap, (float*)d_out);
}

// round 17
// speedup vs baseline: 1.5914x; 1.5914x over previous
#include <cuda_runtime.h>

// ---------------------------------------------------------------------------
// AutoregressiveGRUWithAttention  (B=1024, L=64, T=128, IN=13, H=64, OUT=13)
//
// R16 = R13 with the Wfusion GEMV deleted (it was 3 of 7 busy warps):
//   Phase A (decoder), all reg-resident rows, dots8_r2 broadcast pattern:
//     tid 0-95  (w0-2): Whh row pair (tid, tid+96) on h -> gh
//     tid 96-127 (w3):  Wa row pair (r, r+32) on o -> slg
//     tid 128-159 (w4, lanes 0-25): Wf row oc=lane>>1, batches 4g..4g+3
//                 (g=lane&1) on o -> y(t-1) -> snin + gmem out
//   Phase B (256 threads x 2 (b,j) pairs): gi = Wih·y(t-1) with Wih in
//     registers and snin read as float4 (4 LDS.128/group); fold online
//     softmax; GRU gates; publish h/o. 2 syncs/step.
// Decoder A(0) computes y from o_init (= masked final h), i.e. nin == y(-1).
// Online-softmax attention == reference masked softmax (validated R7-R15).
// ---------------------------------------------------------------------------

typedef unsigned long long ull;

namespace {
constexpr int L_ = 64, T_ = 128, IN_ = 13, H_ = 64, OUT_ = 13, NB_ = 8;
constexpr int THREADS_ = 256, BLOCKS_ = 128;
constexpr int HS_ = 68;              // state row stride
constexpr int GP_ = NB_ * HS_;       // 544 floats per gate plane
constexpr int XT_ = 16, XPB_ = L_ * XT_;

constexpr int SM_SH  = 0;                 // h   [8][68]
constexpr int SM_SO  = SM_SH + GP_;       // o   [8][68]
constexpr int SM_GH  = SM_SO + GP_;       // Whh.h [3][8][68]
constexpr int SM_LG  = SM_GH + 3 * GP_;   // logits [8][68]
constexpr int SM_NIN = SM_LG + GP_;       // y_prev [8][16]
constexpr int SM_SX  = SM_NIN + NB_ * 16; // x [8][1024]
constexpr int SM_FLOATS = SM_SX + NB_ * XPB_;   // 11584 floats = 46.3 KB
}

__device__ __forceinline__ ull fma2_(ull a, ull b, ull c) {
    ull d;
    asm("fma.rn.f32x2 %0, %1, %2, %3;" : "=l"(d) : "l"(a), "l"(b), "l"(c));
    return d;
}
__device__ __forceinline__ float hsum2_(ull a) {
    unsigned lo, hi;
    asm("mov.b64 {%0, %1}, %2;" : "=r"(lo), "=r"(hi) : "l"(a));
    return __uint_as_float(lo) + __uint_as_float(hi);
}
__device__ __forceinline__ float sigmoid_(float a) {
    return __fdividef(1.f, 1.f + __expf(-a));
}
__device__ __forceinline__ float tanh_(float a) {
    float c  = fminf(fmaxf(a, -15.f), 15.f);
    float e2 = __expf(2.f * c);
    return __fdividef(e2 - 1.f, e2 + 1.f);
}

// Two register rows dotted with 8 state vectors (broadcast smem reads).
__device__ __forceinline__ void dots8_r2(const ull (&w)[64], const float* src,
                                         float* dA, float* dB) {
    #pragma unroll
    for (int b = 0; b < 8; b += 2) {
        const float* p0 = src + b * HS_;
        const float* p1 = src + (b + 1) * HS_;
        ull a0 = 0, a1 = 0, c0 = 0, c1 = 0;
        #pragma unroll
        for (int c = 0; c < 16; ++c) {
            ulonglong2 v0 = *(const ulonglong2*)(p0 + 4 * c);
            ulonglong2 v1 = *(const ulonglong2*)(p1 + 4 * c);
            a0 = fma2_(w[2*c],    v0.x, a0); a0 = fma2_(w[2*c+1],    v0.y, a0);
            a1 = fma2_(w[2*c],    v1.x, a1); a1 = fma2_(w[2*c+1],    v1.y, a1);
            c0 = fma2_(w[32+2*c], v0.x, c0); c0 = fma2_(w[32+2*c+1], v0.y, c0);
            c1 = fma2_(w[32+2*c], v1.x, c1); c1 = fma2_(w[32+2*c+1], v1.y, c1);
        }
        dA[b * HS_]       = hsum2_(a0);
        dA[(b + 1) * HS_] = hsum2_(a1);
        dB[b * HS_]       = hsum2_(c0);
        dB[(b + 1) * HS_] = hsum2_(c1);
    }
}

// One register row dotted with batches 4g..4g+3 of src -> y4.
__device__ __forceinline__ void dots4g_r1(const ull* w, const float* src,
                                          int g, float (&y4)[4]) {
    const float* p0 = src + (4 * g + 0) * HS_;
    const float* p1 = src + (4 * g + 1) * HS_;
    const float* p2 = src + (4 * g + 2) * HS_;
    const float* p3 = src + (4 * g + 3) * HS_;
    ull a0 = 0, a1 = 0, a2 = 0, a3 = 0;
    #pragma unroll
    for (int c = 0; c < 16; ++c) {
        ulonglong2 v0 = *(const ulonglong2*)(p0 + 4 * c);
        ulonglong2 v1 = *(const ulonglong2*)(p1 + 4 * c);
        ulonglong2 v2 = *(const ulonglong2*)(p2 + 4 * c);
        ulonglong2 v3 = *(const ulonglong2*)(p3 + 4 * c);
        a0 = fma2_(w[2*c], v0.x, a0); a0 = fma2_(w[2*c+1], v0.y, a0);
        a1 = fma2_(w[2*c], v1.x, a1); a1 = fma2_(w[2*c+1], v1.y, a1);
        a2 = fma2_(w[2*c], v2.x, a2); a2 = fma2_(w[2*c+1], v2.y, a2);
        a3 = fma2_(w[2*c], v3.x, a3); a3 = fma2_(w[2*c+1], v3.y, a3);
    }
    y4[0] = hsum2_(a0); y4[1] = hsum2_(a1);
    y4[2] = hsum2_(a2); y4[3] = hsum2_(a3);
}

__global__ void __launch_bounds__(THREADS_, 1)
gru_attn_kernel(const float* __restrict__ x, const int* __restrict__ lengths,
                const float* __restrict__ Wih, const float* __restrict__ Whh,
                const float* __restrict__ bih, const float* __restrict__ bhh,
                const float* __restrict__ Wf,  const float* __restrict__ bf,
                const float* __restrict__ Wa,  const float* __restrict__ ba,
                float* __restrict__ out)
{
    __shared__ __align__(16) float sm[SM_FLOATS];
    __shared__ int smax;
    float* sh   = sm + SM_SH;
    float* so   = sm + SM_SO;
    float* gh   = sm + SM_GH;
    float* slg  = sm + SM_LG;
    float* snin = sm + SM_NIN;
    float* sx   = sm + SM_SX;

    const int tid  = threadIdx.x;
    const int lane = tid & 31;
    const int b0   = blockIdx.x * NB_;
    const int j2   = tid & 63;
    const int bb   = tid >> 6;                 // 0..3
    const int offg[2] = { bb * HS_ + j2, (4 + bb) * HS_ + j2 };

    // ---- staging
    for (int idx = tid; idx < NB_ * XPB_; idx += THREADS_) {
        int b = idx >> 10, r = idx & 1023, tt = r >> 4, i = r & 15;
        sx[idx] = (i < IN_) ? x[(size_t)(b0 + b) * (L_ * IN_) + tt * IN_ + i] : 0.f;
    }
    for (int idx = tid; idx < GP_; idx += THREADS_) sh[idx] = 0.f;
    if (tid == 0) {
        int m = 0;
        #pragma unroll
        for (int b = 0; b < NB_; ++b) m = max(m, lengths[b0 + b]);
        smax = m;
    }

    // ---- Phase-A role setup (register rows)
    ull w2[64];
    float* dA = gh;
    float* dB = gh;
    float bf_reg = 0.f;
    const bool roleWhh = (tid < 96);
    const bool roleWa  = (tid >= 96 && tid < 128);
    const bool roleWf  = (tid >= 128 && tid < 160 && lane < 2 * OUT_);
    const int  oc_wf = lane >> 1;          // output channel (roleWf)
    const int  g_wf  = lane & 1;           // batch group (roleWf)

    if (roleWhh) {
        const ull* p = (const ull*)(Whh + tid * H_);
        #pragma unroll
        for (int k = 0; k < 32; ++k) w2[k] = p[k];
        p = (const ull*)(Whh + (tid + 96) * H_);
        #pragma unroll
        for (int k = 0; k < 32; ++k) w2[32 + k] = p[k];
        dA = gh + (tid >> 6) * GP_ + (tid & 63);
        dB = gh + ((tid + 96) >> 6) * GP_ + ((tid + 96) & 63);
    } else if (roleWa) {
        const int r0 = tid - 96;
        const ull* p = (const ull*)(Wa + r0 * H_);
        #pragma unroll
        for (int k = 0; k < 32; ++k) w2[k] = p[k];
        p = (const ull*)(Wa + (r0 + 32) * H_);
        #pragma unroll
        for (int k = 0; k < 32; ++k) w2[32 + k] = p[k];
        dA = slg + r0;
        dB = slg + r0 + 32;
    } else if (roleWf) {
        const ull* p = (const ull*)(Wf + oc_wf * H_);
        #pragma unroll
        for (int k = 0; k < 32; ++k) w2[k] = p[k];
        bf_reg = bf[oc_wf];
    }

    // ---- Wih rows for channel j2 (used by every thread in Phase B)
    float wr_[IN_], wz_[IN_], wn_[IN_];
    #pragma unroll
    for (int i = 0; i < IN_; ++i) {
        wr_[i] = Wih[j2 * IN_ + i];
        wz_[i] = Wih[(64 + j2) * IN_ + i];
        wn_[i] = Wih[(128 + j2) * IN_ + i];
    }
    const float brr = bih[j2]          + bhh[j2];
    const float bzz = bih[H_ + j2]     + bhh[H_ + j2];
    const float bni = bih[2 * H_ + j2];
    const float bnh = bhh[2 * H_ + j2];
    const float bav = ba[j2];
    const int len_[2] = { lengths[b0 + bb], lengths[b0 + bb + 4] };

    __syncthreads();
    const int Lmax = smax;

    float h_own[2] = {0.f, 0.f};

    // 13-term dot of register Wih rows with a 16-float vector (float4 reads)
    auto gi13 = [&](const float* v16, float& gr, float& gz, float& gn) {
        const float4* v = (const float4*)v16;
        float4 v0 = v[0], v1 = v[1], v2 = v[2], v3 = v[3];
        gr = ((wr_[0]*v0.x + wr_[1]*v0.y) + (wr_[2]*v0.z + wr_[3]*v0.w))
           + ((wr_[4]*v1.x + wr_[5]*v1.y) + (wr_[6]*v1.z + wr_[7]*v1.w))
           + ((wr_[8]*v2.x + wr_[9]*v2.y) + (wr_[10]*v2.z + wr_[11]*v2.w))
           + wr_[12]*v3.x;
        gz = ((wz_[0]*v0.x + wz_[1]*v0.y) + (wz_[2]*v0.z + wz_[3]*v0.w))
           + ((wz_[4]*v1.x + wz_[5]*v1.y) + (wz_[6]*v1.z + wz_[7]*v1.w))
           + ((wz_[8]*v2.x + wz_[9]*v2.y) + (wz_[10]*v2.z + wz_[11]*v2.w))
           + wz_[12]*v3.x;
        gn = ((wn_[0]*v0.x + wn_[1]*v0.y) + (wn_[2]*v0.z + wn_[3]*v0.w))
           + ((wn_[4]*v1.x + wn_[5]*v1.y) + (wn_[6]*v1.z + wn_[7]*v1.w))
           + ((wn_[8]*v2.x + wn_[9]*v2.y) + (wn_[10]*v2.z + wn_[11]*v2.w))
           + wn_[12]*v3.x;
    };

    // =======================  ENCODER  =======================
    for (int t = 0; t < Lmax; ++t) {
        if (roleWhh) dots8_r2(w2, sh, dA, dB);     // gh = Whh.h
        __syncthreads();
        #pragma unroll
        for (int g = 0; g < 2; ++g) {
            const int b = 4 * g + bb, off = offg[g];
            float gr, gz, gn;
            gi13(sx + b * XPB_ + t * XT_, gr, gz, gn);
            float r = sigmoid_(gh[off] + gr + brr);
            float z = sigmoid_(gh[GP_ + off] + gz + bzz);
            float n = tanh_((gn + bni) + r * (gh[2 * GP_ + off] + bnh));
            float hne = (1.f - z) * n + z * h_own[g];
            h_own[g] = (t < len_[g]) ? hne : h_own[g];
            sh[off] = h_own[g];
        }
        __syncthreads();
    }

    // o_init = outs[-1]: nonzero only when length == L (then equals final h)
    so[offg[0]] = (len_[0] == L_) ? h_own[0] : 0.f;
    so[offg[1]] = (len_[1] == L_) ? h_own[1] : 0.f;
    __syncthreads();

    // =======================  DECODER  =======================
    float m_[2] = {-1e30f, -1e30f}, s_[2] = {0.f, 0.f};
    float a_[2] = {0.f, 0.f}, op_[2] = {0.f, 0.f};

    for (int t = 0; t <= T_; ++t) {
        // ---- Phase A on (h(t-1), o(t-1)): gh, slg, y(t-1)
        if (roleWhh) {
            dots8_r2(w2, sh, dA, dB);
        } else if (roleWa) {
            dots8_r2(w2, so, dA, dB);
        } else if (roleWf) {
            float y4[4];
            dots4g_r1(w2, so, g_wf, y4);           // y(t-1); at t=0 this is nin
            #pragma unroll
            for (int bi = 0; bi < 4; ++bi) {
                const int b = 4 * g_wf + bi;
                float y = y4[bi] + bf_reg;
                snin[b * 16 + oc_wf] = y;
                if (t > 0)
                    out[((size_t)(b0 + b) * T_ + (t - 1)) * OUT_ + oc_wf] = y;
            }
        }
        __syncthreads();

        // ---- Phase B
        if (t < T_) {
            #pragma unroll
            for (int g = 0; g < 2; ++g) {
                const int b = 4 * g + bb, off = offg[g];
                float gr, gz, gn;
                gi13(snin + b * 16, gr, gz, gn);   // gi = Wih . y(t-1)
                // fold buf[t-1] = o(t-1) into online softmax
                float l = slg[off] + bav;
                if (t > 0) {
                    float mn = fmaxf(m_[g], l);
                    float c = __expf(m_[g] - mn), e = __expf(l - mn);
                    s_[g] = s_[g] * c + e;
                    a_[g] = a_[g] * c + e * op_[g];
                    m_[g] = mn;
                }
                float r = sigmoid_(gh[off] + gr + brr);
                float z = sigmoid_(gh[GP_ + off] + gz + bzz);
                float n = tanh_((gn + bni) + r * (gh[2 * GP_ + off] + bnh));
                float hne = (1.f - z) * n + z * h_own[g];
                float att = (t == 0) ? 0.f : __fdividef(a_[g], s_[g]);
                float ov = hne + att;
                h_own[g] = hne;  op_[g] = ov;
                sh[off] = hne;   so[off] = ov;
            }
        }
        __syncthreads();
    }
}

extern "C" void kernel_launch(void* const* d_in, const int* in_sizes, int n_in,
                              void* d_out, int out_size) {
    const float* xp   = nullptr;
    const int*   lenp = nullptr;
    const float *Wihp = nullptr, *Whhp = nullptr, *bihp = nullptr, *bhhp = nullptr;
    const float *Wfp = nullptr, *bfp = nullptr, *Wap = nullptr, *bap = nullptr;

    for (int i = 0; i < n_in; ++i) {
        switch (in_sizes[i]) {
            case 1024 * 64 * 13: xp   = (const float*)d_in[i]; break;
            case 1024:           lenp = (const int*)d_in[i];   break;
            case 192 * 13:       Wihp = (const float*)d_in[i]; break;
            case 192 * 64:       Whhp = (const float*)d_in[i]; break;
            case 192:
                if (!bihp) bihp = (const float*)d_in[i];
                else       bhhp = (const float*)d_in[i];
                break;
            case 13 * 64:        Wfp  = (const float*)d_in[i]; break;
            case 13:             bfp  = (const float*)d_in[i]; break;
            case 64 * 64:        Wap  = (const float*)d_in[i]; break;
            case 64:             bap  = (const float*)d_in[i]; break;
            default: break;   // output_length scalar -> T=128 hardcoded
        }
    }

    gru_attn_kernel<<<BLOCKS_, THREADS_>>>(
        xp, lenp, Wihp, Whhp, bihp, bhhp, Wfp, bfp, Wap, bap, (float*)d_out);
}